// round 17
// baseline (speedup 1.0000x reference)
#include <cuda_runtime.h>
#include <cuda_bf16.h>

// Problem: B=512, S=512, I=64, C=4, H=100, O=7
// out = [output (512*7)] ++ [hidden_states (512*512*100)]

#define ULL unsigned long long

// ---------------- scratch (device globals; no runtime allocation) -----------
__device__ float g_xf[512 * 512 * 100];
__device__ float g_xh[512 * 512 * 100];

// ---------------- helpers ---------------------------------------------------
__device__ __forceinline__ ULL fma2(ULL a, ULL b, ULL c) {
    ULL d;
    asm("fma.rn.f32x2 %0, %1, %2, %3;" : "=l"(d) : "l"(a), "l"(b), "l"(c));
    return d;
}
__device__ __forceinline__ float hsum2(ULL a) {
    float lo, hi;
    asm("mov.b64 {%0,%1}, %2;" : "=f"(lo), "=f"(hi) : "l"(a));
    return lo + hi;
}
__device__ __forceinline__ void unpack2(ULL a, float& lo, float& hi) {
    asm("mov.b64 {%0,%1}, %2;" : "=f"(lo), "=f"(hi) : "l"(a));
}
__device__ __forceinline__ ULL dup2(float v) {
    ULL d;
    asm("mov.b64 %0, {%1,%1};" : "=l"(d) : "f"(v));
    return d;
}
__device__ __forceinline__ float sigmoidf_(float v) {
    return __fdividef(1.f, 1.f + __expf(-v));
}
__device__ __forceinline__ float tanhf_(float v) {
    return 1.f - __fdividef(2.f, __expf(2.f * v) + 1.f);
}

// ---------------- K1: pre-GEMM v6 (R16 version: best measured, 227us) --------
#define PRE_XP    257
#define PRE_XSF   (64 * PRE_XP)
#define PRE_SP    36
#define PRE_UF    (256 * PRE_SP)
#define PRE_CBF   256
#define PRE_SMEM  ((PRE_XSF + PRE_UF + PRE_CBF) * 4)

__global__ void __launch_bounds__(256, 2)
pre_kernel(const float* __restrict__ x, const float* __restrict__ ctx,
           const float* __restrict__ Wf_w, const float* __restrict__ Wf_b,
           const float* __restrict__ Wh_w, const float* __restrict__ Wh_b)
{
    extern __shared__ float sm[];
    float* xs  = sm;                      // [64][257]  x transposed
    float* ws  = sm + PRE_XSF;            // [64][68]   w transposed (union lo)
    float* sht = sm + PRE_XSF;            // [256][36]  store staging (union)
    float* cb  = sm + PRE_XSF + PRE_UF;   // [256]      ctx-folded bias

    const int tid = threadIdx.x;
    const int pg = tid & 63;
    const int jg = tid >> 6;
    const size_t pbase = (size_t)blockIdx.x * 256;

    {
        int r = tid;
        float v = 0.f;
        if (r < 200) {
            const float* W = (r < 100) ? (Wf_w + r * 168) : (Wh_w + (r - 100) * 168);
            v = (r < 100) ? Wf_b[r] : Wh_b[r - 100];
            #pragma unroll
            for (int c = 0; c < 4; c++) v += ctx[c] * W[64 + c];
        }
        cb[r] = v;
    }

    for (int idx = tid; idx < 4096; idx += 256) {
        int p = idx >> 4, k4 = (idx & 15) << 2;
        float4 v = *(const float4*)(x + (pbase + p) * 64 + k4);
        xs[(k4 + 0) * PRE_XP + p] = v.x;
        xs[(k4 + 1) * PRE_XP + p] = v.y;
        xs[(k4 + 2) * PRE_XP + p] = v.z;
        xs[(k4 + 3) * PRE_XP + p] = v.w;
    }
    __syncthreads();

    #pragma unroll 1
    for (int pass = 0; pass < 4; pass++) {
        for (int idx = tid; idx < 1024; idx += 256) {
            int row = idx >> 4, k4 = (idx & 15) << 2;
            int rg = pass * 64 + row;
            int rc = (rg < 200) ? rg : 199;
            const float* W = (rc < 100) ? (Wf_w + rc * 168) : (Wh_w + (rc - 100) * 168);
            float4 v = *(const float4*)(W + k4);
            ws[(k4 + 0) * 68 + row] = v.x;
            ws[(k4 + 1) * 68 + row] = v.y;
            ws[(k4 + 2) * 68 + row] = v.z;
            ws[(k4 + 3) * 68 + row] = v.w;
        }
        __syncthreads();

        ULL acc[8][4];
        #pragma unroll
        for (int a = 0; a < 8; a++)
            #pragma unroll
            for (int b = 0; b < 4; b++) acc[a][b] = 0ull;

        #pragma unroll 4
        for (int k = 0; k < 64; k++) {
            float xv0 = xs[k * PRE_XP + pg];
            float xv1 = xs[k * PRE_XP + pg + 64];
            float xv2 = xs[k * PRE_XP + pg + 128];
            float xv3 = xs[k * PRE_XP + pg + 192];
            ulonglong2 wa = *(const ulonglong2*)(ws + k * 68 + jg * 16);
            ulonglong2 wb = *(const ulonglong2*)(ws + k * 68 + jg * 16 + 4);
            ulonglong2 wc = *(const ulonglong2*)(ws + k * 68 + jg * 16 + 8);
            ulonglong2 wd = *(const ulonglong2*)(ws + k * 68 + jg * 16 + 12);
            ULL d0 = dup2(xv0), d1 = dup2(xv1), d2 = dup2(xv2), d3 = dup2(xv3);
            acc[0][0] = fma2(wa.x, d0, acc[0][0]);
            acc[0][1] = fma2(wa.x, d1, acc[0][1]);
            acc[0][2] = fma2(wa.x, d2, acc[0][2]);
            acc[0][3] = fma2(wa.x, d3, acc[0][3]);
            acc[1][0] = fma2(wa.y, d0, acc[1][0]);
            acc[1][1] = fma2(wa.y, d1, acc[1][1]);
            acc[1][2] = fma2(wa.y, d2, acc[1][2]);
            acc[1][3] = fma2(wa.y, d3, acc[1][3]);
            acc[2][0] = fma2(wb.x, d0, acc[2][0]);
            acc[2][1] = fma2(wb.x, d1, acc[2][1]);
            acc[2][2] = fma2(wb.x, d2, acc[2][2]);
            acc[2][3] = fma2(wb.x, d3, acc[2][3]);
            acc[3][0] = fma2(wb.y, d0, acc[3][0]);
            acc[3][1] = fma2(wb.y, d1, acc[3][1]);
            acc[3][2] = fma2(wb.y, d2, acc[3][2]);
            acc[3][3] = fma2(wb.y, d3, acc[3][3]);
            acc[4][0] = fma2(wc.x, d0, acc[4][0]);
            acc[4][1] = fma2(wc.x, d1, acc[4][1]);
            acc[4][2] = fma2(wc.x, d2, acc[4][2]);
            acc[4][3] = fma2(wc.x, d3, acc[4][3]);
            acc[5][0] = fma2(wc.y, d0, acc[5][0]);
            acc[5][1] = fma2(wc.y, d1, acc[5][1]);
            acc[5][2] = fma2(wc.y, d2, acc[5][2]);
            acc[5][3] = fma2(wc.y, d3, acc[5][3]);
            acc[6][0] = fma2(wd.x, d0, acc[6][0]);
            acc[6][1] = fma2(wd.x, d1, acc[6][1]);
            acc[6][2] = fma2(wd.x, d2, acc[6][2]);
            acc[6][3] = fma2(wd.x, d3, acc[6][3]);
            acc[7][0] = fma2(wd.y, d0, acc[7][0]);
            acc[7][1] = fma2(wd.y, d1, acc[7][1]);
            acc[7][2] = fma2(wd.y, d2, acc[7][2]);
            acc[7][3] = fma2(wd.y, d3, acc[7][3]);
        }
        __syncthreads();

        const int rb = pass * 64 + jg * 16;
        #pragma unroll 1
        for (int half = 0; half < 2; half++) {
            if ((jg >> 1) == half) {
                const int colbase = (jg & 1) * 16;
                #pragma unroll
                for (int i = 0; i < 4; i++) {
                    int p = pg + 64 * i;
                    #pragma unroll
                    for (int q = 0; q < 4; q++) {
                        float lo0, hi0, lo1, hi1;
                        unpack2(acc[2 * q][i],     lo0, hi0);
                        unpack2(acc[2 * q + 1][i], lo1, hi1);
                        float b0 = cb[rb + 4 * q + 0];
                        float b1 = cb[rb + 4 * q + 1];
                        float b2 = cb[rb + 4 * q + 2];
                        float b3 = cb[rb + 4 * q + 3];
                        *(float4*)&sht[p * PRE_SP + colbase + 4 * q] =
                            make_float4(lo0 + b0, hi0 + b1, lo1 + b2, hi1 + b3);
                    }
                }
            }
            __syncthreads();

            for (int f = tid; f < 2048; f += 256) {
                int pos = f >> 3, r4 = f & 7;
                int rg4 = pass * 64 + half * 32 + r4 * 4;
                float4 v = *(const float4*)&sht[pos * PRE_SP + r4 * 4];
                size_t po = (pbase + pos) * 100;
                if (rg4 < 100)       *(float4*)(g_xf + po + rg4)       = v;
                else if (rg4 < 200)  *(float4*)(g_xh + po + rg4 - 100) = v;
            }
            __syncthreads();
        }
    }
}

// ---------------- K2: scan, 2 j-outputs per thread ---------------------------
// 128 blocks x 4 batch rows x 400 threads: thread (jp = tid%50, c = tid/50).
// Thread computes chunks of the dots for j0=2jp and j1=2jp+1 over
// k in [16c, 16c+16) (h padded to 128; c=6: 2 real pairs, c=7: zero).
// Key change vs R4: every h LDS.128 feeds FOUR weight fma2 (2 j x pair) ->
// LDS wavefronts per MV phase drop 350 -> 200 per SM (the LSU was the
// dominant per-step cost). Same 4-phase/4-barrier skeleton.
// Act bijection: thread (jp,c) owns (j_act = 2jp + (c&1), r_act = c>>1).
__global__ void __launch_bounds__(400, 1)
scan_kernel(const float* __restrict__ Wf_w, const float* __restrict__ Wh_w,
            float* __restrict__ hidden)
{
    const int tid = threadIdx.x;
    const int c  = tid / 50;         // 0..7 (k-chunk)
    const int jp = tid - c * 50;     // 0..49 (j-pair)
    const int kb = 16 * c;
    const int rbase = blockIdx.x * 4;

    __shared__ __align__(16) float sh_h[4][128];
    __shared__ __align__(16) float sh_fh[4][128];
    __shared__ __align__(16) float sh_p[8][400];   // [chunk][jp*8 + jj*4 + row]

    // register-resident weights: 2 j x 8 pairs x 2 gates = 32 ULL (64 regs)
    ULL wfA[8], wfB[8], whA[8], whB[8];
    {
        const int lc = (c < 6) ? 8 : ((c == 6) ? 2 : 0);  // real pairs (k<=99)
        const int j0 = 2 * jp, j1 = 2 * jp + 1;
        const ULL* pfA = (const ULL*)(Wf_w + j0 * 168 + 68 + kb);
        const ULL* pfB = (const ULL*)(Wf_w + j1 * 168 + 68 + kb);
        const ULL* phA = (const ULL*)(Wh_w + j0 * 168 + 68 + kb);
        const ULL* phB = (const ULL*)(Wh_w + j1 * 168 + 68 + kb);
        #pragma unroll
        for (int t = 0; t < 8; t++) {
            wfA[t] = (t < lc) ? pfA[t] : 0ull;
            wfB[t] = (t < lc) ? pfB[t] : 0ull;
            whA[t] = (t < lc) ? phA[t] : 0ull;
            whB[t] = (t < lc) ? phB[t] : 0ull;
        }
    }

    // h0 = 0 (also zeroes k=100..127 padding)
    for (int idx = tid; idx < 4 * 128; idx += 400) {
        (&sh_h[0][0])[idx]  = 0.f;
        (&sh_fh[0][0])[idx] = 0.f;
    }
    __syncthreads();

    const int j_act = 2 * jp + (c & 1);
    const int r_act = c >> 1;
    const size_t xbase = (size_t)(rbase + r_act) * 51200 + j_act;
    float xf_cur = g_xf[xbase];
    float xh_cur = g_xh[xbase];
    float xf_nxt = 0.f, xh_nxt = 0.f, fg = 0.f, hold = 0.f;

    #pragma unroll 1
    for (int s = 0; s < 512; s++) {
        // -- matvec 1: Wf_h . h  (2 j x 4 rows, own chunk)
        {
            ULL a00 = 0ull, a01 = 0ull, a02 = 0ull, a03 = 0ull;
            ULL a10 = 0ull, a11 = 0ull, a12 = 0ull, a13 = 0ull;
            #pragma unroll
            for (int t = 0; t < 4; t++) {
                ulonglong2 h0 = *(const ulonglong2*)&sh_h[0][kb + 4 * t];
                ulonglong2 h1 = *(const ulonglong2*)&sh_h[1][kb + 4 * t];
                ulonglong2 h2 = *(const ulonglong2*)&sh_h[2][kb + 4 * t];
                ulonglong2 h3 = *(const ulonglong2*)&sh_h[3][kb + 4 * t];
                a00 = fma2(wfA[2 * t], h0.x, a00); a00 = fma2(wfA[2 * t + 1], h0.y, a00);
                a01 = fma2(wfA[2 * t], h1.x, a01); a01 = fma2(wfA[2 * t + 1], h1.y, a01);
                a02 = fma2(wfA[2 * t], h2.x, a02); a02 = fma2(wfA[2 * t + 1], h2.y, a02);
                a03 = fma2(wfA[2 * t], h3.x, a03); a03 = fma2(wfA[2 * t + 1], h3.y, a03);
                a10 = fma2(wfB[2 * t], h0.x, a10); a10 = fma2(wfB[2 * t + 1], h0.y, a10);
                a11 = fma2(wfB[2 * t], h1.x, a11); a11 = fma2(wfB[2 * t + 1], h1.y, a11);
                a12 = fma2(wfB[2 * t], h2.x, a12); a12 = fma2(wfB[2 * t + 1], h2.y, a12);
                a13 = fma2(wfB[2 * t], h3.x, a13); a13 = fma2(wfB[2 * t + 1], h3.y, a13);
            }
            float* p = &sh_p[c][jp * 8];
            *(float4*)(p)     = make_float4(hsum2(a00), hsum2(a01), hsum2(a02), hsum2(a03));
            *(float4*)(p + 4) = make_float4(hsum2(a10), hsum2(a11), hsum2(a12), hsum2(a13));
        }
        __syncthreads();  // (1)

        // -- act 1: f-gate, f*h  (thread owns (j_act, r_act))
        {
            const int po = jp * 8 + (c & 1) * 4 + r_act;
            float sum = sh_p[0][po] + sh_p[1][po] + sh_p[2][po] + sh_p[3][po]
                      + sh_p[4][po] + sh_p[5][po] + sh_p[6][po] + sh_p[7][po];
            fg = sigmoidf_(sum + xf_cur);
            hold = sh_h[r_act][j_act];
            sh_fh[r_act][j_act] = fg * hold;
            int sp = (s < 511) ? s + 1 : 511;
            xf_nxt = g_xf[xbase + (size_t)sp * 100];
            xh_nxt = g_xh[xbase + (size_t)sp * 100];
        }
        __syncthreads();  // (2)

        // -- matvec 2: Wh_h . (f*h)
        {
            ULL a00 = 0ull, a01 = 0ull, a02 = 0ull, a03 = 0ull;
            ULL a10 = 0ull, a11 = 0ull, a12 = 0ull, a13 = 0ull;
            #pragma unroll
            for (int t = 0; t < 4; t++) {
                ulonglong2 h0 = *(const ulonglong2*)&sh_fh[0][kb + 4 * t];
                ulonglong2 h1 = *(const ulonglong2*)&sh_fh[1][kb + 4 * t];
                ulonglong2 h2 = *(const ulonglong2*)&sh_fh[2][kb + 4 * t];
                ulonglong2 h3 = *(const ulonglong2*)&sh_fh[3][kb + 4 * t];
                a00 = fma2(whA[2 * t], h0.x, a00); a00 = fma2(whA[2 * t + 1], h0.y, a00);
                a01 = fma2(whA[2 * t], h1.x, a01); a01 = fma2(whA[2 * t + 1], h1.y, a01);
                a02 = fma2(whA[2 * t], h2.x, a02); a02 = fma2(whA[2 * t + 1], h2.y, a02);
                a03 = fma2(whA[2 * t], h3.x, a03); a03 = fma2(whA[2 * t + 1], h3.y, a03);
                a10 = fma2(whB[2 * t], h0.x, a10); a10 = fma2(whB[2 * t + 1], h0.y, a10);
                a11 = fma2(whB[2 * t], h1.x, a11); a11 = fma2(whB[2 * t + 1], h1.y, a11);
                a12 = fma2(whB[2 * t], h2.x, a12); a12 = fma2(whB[2 * t + 1], h2.y, a12);
                a13 = fma2(whB[2 * t], h3.x, a13); a13 = fma2(whB[2 * t + 1], h3.y, a13);
            }
            float* p = &sh_p[c][jp * 8];
            *(float4*)(p)     = make_float4(hsum2(a00), hsum2(a01), hsum2(a02), hsum2(a03));
            *(float4*)(p + 4) = make_float4(hsum2(a10), hsum2(a11), hsum2(a12), hsum2(a13));
        }
        __syncthreads();  // (3)

        // -- act 2: h update + store
        {
            const int po = jp * 8 + (c & 1) * 4 + r_act;
            float sum = sh_p[0][po] + sh_p[1][po] + sh_p[2][po] + sh_p[3][po]
                      + sh_p[4][po] + sh_p[5][po] + sh_p[6][po] + sh_p[7][po];
            float ht = tanhf_(sum + xh_cur);
            float hn = hold + fg * (ht - hold);
            sh_h[r_act][j_act] = hn;
            hidden[((size_t)(rbase + r_act) * 512 + s) * 100 + j_act] = hn;
            xf_cur = xf_nxt;
            xh_cur = xh_nxt;
        }
        __syncthreads();  // (4)
    }
}

// ---------------- K3: output head (warp per output) --------------------------
__global__ void head_kernel(const float* __restrict__ hidden,
                            const float* __restrict__ ro_w,
                            const float* __restrict__ ro_b,
                            float* __restrict__ out)
{
    int warp = (blockIdx.x * blockDim.x + threadIdx.x) >> 5;
    int lane = threadIdx.x & 31;
    if (warp >= 512 * 7) return;
    int b = warp / 7, o = warp - b * 7;
    const float* h = hidden + ((size_t)b * 512 + 511) * 100;
    const float* w = ro_w + o * 100;
    float acc = 0.f;
    for (int k = lane; k < 100; k += 32) acc += h[k] * w[k];
    #pragma unroll
    for (int d = 16; d; d >>= 1) acc += __shfl_xor_sync(0xFFFFFFFFu, acc, d);
    if (lane == 0) out[b * 7 + o] = acc + ro_b[o];
}

// ---------------- launch -----------------------------------------------------
extern "C" void kernel_launch(void* const* d_in, const int* in_sizes, int n_in,
                              void* d_out, int out_size)
{
    (void)in_sizes; (void)n_in; (void)out_size;
    const float* x     = (const float*)d_in[0];
    const float* ctx   = (const float*)d_in[1];
    const float* Wf_w  = (const float*)d_in[2];
    const float* Wf_b  = (const float*)d_in[3];
    const float* Wh_w  = (const float*)d_in[4];
    const float* Wh_b  = (const float*)d_in[5];
    const float* ro_w  = (const float*)d_in[6];
    const float* ro_b  = (const float*)d_in[7];

    float* out    = (float*)d_out;
    float* hidden = out + 512 * 7;

    cudaFuncSetAttribute(pre_kernel,
                         cudaFuncAttributeMaxDynamicSharedMemorySize, PRE_SMEM);
    pre_kernel<<<1024, 256, PRE_SMEM>>>(x, ctx, Wf_w, Wf_b, Wh_w, Wh_b);
    scan_kernel<<<128, 400>>>(Wf_w, Wh_w, hidden);
    head_kernel<<<448, 256>>>(hidden, ro_w, ro_b, out);
}